// round 14
// baseline (speedup 1.0000x reference)
#include <cuda_runtime.h>
#include <cstdint>
#include <cstddef>

typedef unsigned long long u64t;

__device__ float g_P1[16777216];
__device__ float g_P2[8388608];
__device__ float g_A3[16777216];
__device__ float g_V [8388608];
__device__ float g_VP[8388608];
__device__ float g_Wbig[2359296];  // [2048][1152] unit-major rows, K-padded
__device__ float g_WhaT[262144];
__device__ float g_embT[384000];
__device__ float g_xfull[36864];   // [1152][32]: emb80|O512|h512|pad
__device__ float g_cT[2][16384];
__device__ float g_hc[32768];      // [1024][32]: h | ctx
__device__ float g_hp[16384];
__device__ float g_es[16384];
__device__ unsigned g_barrier;

__device__ __forceinline__ float ftanh(float x){float y;asm("tanh.approx.f32 %0,%1;":"=f"(y):"f"(x));return y;}
__device__ __forceinline__ float sigf(float x){return 1.0f/(1.0f+__expf(-x));}
__device__ __forceinline__ u64t dupf(float v){u64t r;asm("mov.b64 %0,{%1,%1};":"=l"(r):"f"(v));return r;}
__device__ __forceinline__ void ffma2(u64t&a,u64t x,u64t w){asm("fma.rn.f32x2 %0,%1,%2,%3;":"=l"(a):"l"(x),"l"(w),"l"(a));}
__device__ __forceinline__ float2 unpk(u64t a){float2 f;asm("mov.b64 {%0,%1},%2;":"=f"(f.x),"=f"(f.y):"l"(a));return f;}

// ================= conv3x3+bias+relu(+pool)(+NHWC), R6 body =================
template<int IC,int ICS,bool POOL,bool TRANS>
__device__ __forceinline__ void conv_body(const float* __restrict__ in,
    const float* __restrict__ w, const float* __restrict__ bias,
    float* __restrict__ out, int H, int W, int OC){
  __shared__ __align__(16) float wS[ICS][9][64];
  __shared__ __align__(16) float inS[ICS][4][66];
  const int tid=threadIdx.x, OCt=OC>>6, oct=blockIdx.z%OCt, n=blockIdx.z/OCt;
  const int ocb=oct*64, y0=blockIdx.y*2, x0=blockIdx.x*64;
  const int ocg=tid>>5, lane=tid&31, lane2=lane*2;
  u64t acc2[4][2][2];
#pragma unroll
  for(int op=0;op<4;op++){acc2[op][0][0]=0ull;acc2[op][0][1]=0ull;acc2[op][1][0]=0ull;acc2[op][1][1]=0ull;}
  for(int icb=0;icb<IC;icb+=ICS){
    for(int i=tid;i<ICS*9*64;i+=256){
      int oc=i/(ICS*9), rem=i-oc*(ICS*9), ic=rem/9, k=rem-ic*9;
      wS[ic][k][oc]=w[((size_t)(ocb+oc)*IC+icb+ic)*9+k];
    }
    for(int i=tid;i<ICS*4*66;i+=256){
      int ic=i/264, rem=i-ic*264, r=rem/66, x=rem-r*66;
      int gy=y0-1+r, gx=x0-1+x; float v=0.f;
      if(gy>=0&&gy<H&&gx>=0&&gx<W) v=in[((size_t)(n*IC+icb+ic)*H+gy)*W+gx];
      inS[ic][r][x]=v;
    }
    __syncthreads();
#pragma unroll
    for(int ic=0;ic<ICS;ic++){
#pragma unroll
      for(int ky=0;ky<3;ky++){
        float2 p0=*(const float2*)&inS[ic][ky][lane2];
        float2 p1=*(const float2*)&inS[ic][ky][lane2+2];
        float2 q0=*(const float2*)&inS[ic][ky+1][lane2];
        float2 q1=*(const float2*)&inS[ic][ky+1][lane2+2];
        u64t dv0=dupf(p0.x),dv1=dupf(p0.y),dv2=dupf(p1.x),dv3=dupf(p1.y);
        u64t du0=dupf(q0.x),du1=dupf(q0.y),du2=dupf(q1.x),du3=dupf(q1.y);
#pragma unroll
        for(int op=0;op<4;op++){
          u64t w0=*(const u64t*)&wS[ic][ky*3+0][ocg*8+op*2];
          u64t w1=*(const u64t*)&wS[ic][ky*3+1][ocg*8+op*2];
          u64t w2=*(const u64t*)&wS[ic][ky*3+2][ocg*8+op*2];
          ffma2(acc2[op][0][0],dv0,w0); ffma2(acc2[op][0][0],dv1,w1); ffma2(acc2[op][0][0],dv2,w2);
          ffma2(acc2[op][0][1],dv1,w0); ffma2(acc2[op][0][1],dv2,w1); ffma2(acc2[op][0][1],dv3,w2);
          ffma2(acc2[op][1][0],du0,w0); ffma2(acc2[op][1][0],du1,w1); ffma2(acc2[op][1][0],du2,w2);
          ffma2(acc2[op][1][1],du1,w0); ffma2(acc2[op][1][1],du2,w1); ffma2(acc2[op][1][1],du3,w2);
        }
      }
    }
    __syncthreads();
  }
  float acc[8][2][2];
#pragma unroll
  for(int op=0;op<4;op++)
#pragma unroll
    for(int r=0;r<2;r++)
#pragma unroll
      for(int c=0;c<2;c++){
        float2 f=unpk(acc2[op][r][c]);
        acc[op*2][r][c]=f.x; acc[op*2+1][r][c]=f.y;
      }
  const int oc0=ocb+ocg*8;
  if(POOL){
    int py=y0>>1, px=(x0>>1)+lane; float pv[8];
#pragma unroll
    for(int o=0;o<8;o++){
      float bz=bias[oc0+o];
      pv[o]=fmaxf(fmaxf(fmaxf(acc[o][0][0]+bz,0.f),fmaxf(acc[o][0][1]+bz,0.f)),
                  fmaxf(fmaxf(acc[o][1][0]+bz,0.f),fmaxf(acc[o][1][1]+bz,0.f)));
    }
    if(TRANS){
      int l=py*(W>>1)+px;
      float* dst=g_V+((size_t)(n*((H>>1)*(W>>1))+l))*OC+oc0;
      *(float4*)&dst[0]=make_float4(pv[0],pv[1],pv[2],pv[3]);
      *(float4*)&dst[4]=make_float4(pv[4],pv[5],pv[6],pv[7]);
    }else{
      int Hp=H>>1,Wp=W>>1;
#pragma unroll
      for(int o=0;o<8;o++) out[((size_t)(n*OC+oc0+o)*Hp+py)*Wp+px]=pv[o];
    }
  }else{
#pragma unroll
    for(int o=0;o<8;o++){
      float bz=bias[oc0+o];
#pragma unroll
      for(int r=0;r<2;r++)
        *(float2*)&out[((size_t)(n*OC+oc0+o)*H+y0+r)*W+x0+lane2]=
          make_float2(fmaxf(acc[o][r][0]+bz,0.f),fmaxf(acc[o][r][1]+bz,0.f));
    }
  }
}
__global__ void __launch_bounds__(256) conv1_k(const float* X,const float* w,const float* b){conv_body<1,1,true,false>(X,w,b,g_P1,64,512,64);}
__global__ void __launch_bounds__(256) conv2_k(const float* w,const float* b){conv_body<64,8,true,false>(g_P1,w,b,g_P2,32,256,128);}
__global__ void __launch_bounds__(256) conv3_k(const float* w,const float* b){conv_body<128,8,false,false>(g_P2,w,b,g_A3,16,128,256);}
__global__ void __launch_bounds__(256) conv4_k(const float* w,const float* b){conv_body<256,8,true,true>(g_A3,w,b,g_V,16,128,512);}

// ==================== Vproj = V @ Wv + b, 64x64x16 tile =====================
__global__ void __launch_bounds__(256) vproj_k(const float* __restrict__ Bm,const float* __restrict__ bias){
  __shared__ float As[16][68]; __shared__ float Bs[16][64];
  int tid=threadIdx.x, m0=blockIdx.x*64, n0=blockIdx.y*64;
  int mi=tid>>4, ni=tid&15;
  float acc[4][4];
#pragma unroll
  for(int i=0;i<4;i++){acc[i][0]=acc[i][1]=acc[i][2]=acc[i][3]=0.f;}
  int arow=tid>>2, akq=(tid&3)*4, bk=tid>>4, bn=(tid&15)*4;
  for(int kb=0;kb<512;kb+=16){
    float4 a4=*(const float4*)&g_V[(size_t)(m0+arow)*512+kb+akq];
    As[akq+0][arow]=a4.x; As[akq+1][arow]=a4.y; As[akq+2][arow]=a4.z; As[akq+3][arow]=a4.w;
    *(float4*)&Bs[bk][bn]=*(const float4*)&Bm[(size_t)(kb+bk)*512+n0+bn];
    __syncthreads();
#pragma unroll
    for(int k=0;k<16;k++){
      float4 av=*(const float4*)&As[k][mi*4];
      float4 bv=*(const float4*)&Bs[k][ni*4];
      float am[4]={av.x,av.y,av.z,av.w}, bm[4]={bv.x,bv.y,bv.z,bv.w};
#pragma unroll
      for(int i=0;i<4;i++)
#pragma unroll
        for(int j=0;j<4;j++) acc[i][j]=fmaf(am[i],bm[j],acc[i][j]);
    }
    __syncthreads();
  }
  float4 b4=*(const float4*)&bias[n0+ni*4]; float bb[4]={b4.x,b4.y,b4.z,b4.w};
#pragma unroll
  for(int i=0;i<4;i++)
    *(float4*)&g_VP[(size_t)(m0+mi*4+i)*512+n0+ni*4]=
      make_float4(acc[i][0]+bb[0],acc[i][1]+bb[1],acc[i][2]+bb[2],acc[i][3]+bb[3]);
}

// ============================ setup =========================================
__global__ void embT_k(const int* __restrict__ labels,const float* __restrict__ E){
  int u=blockIdx.x*256+threadIdx.x; if(u>=150*2560) return;
  int t=u/2560, rem=u%2560, j=rem>>5, b=rem&31;
  int id=(t==0)?497:labels[b*150+t-1];
  g_embT[u]=E[id*80+j];
}
__global__ void whaT_k(const float* __restrict__ Wha){
  int u=blockIdx.x*256+threadIdx.x; if(u>=262144) return;
  int h=u>>9, be=u&511; g_WhaT[be*512+h]=Wha[u];
}
__global__ void wbig_k(const float* __restrict__ Wx,const float* __restrict__ Wh){
  int u=blockIdx.x*256+threadIdx.x; if(u>=2048*1152) return;
  int rp=u/1152, k=u-rp*1152;
  int unit=rp>>2, g=rp&3, orig=g*512+unit;
  float v=0.f;
  if(k<592) v=Wx[(size_t)orig*592+k];
  else if(k<1104) v=Wh[(size_t)orig*512+(k-592)];
  g_Wbig[u]=v;
}
__global__ void init_k(){
  int u=blockIdx.x*256+threadIdx.x;
  if(u<36864) g_xfull[u]=(u<2560)?g_embT[u]:0.f;
  else if(u<36864+16384) g_cT[0][u-36864]=0.f;
}
__global__ void reset_k(){ g_barrier=0u; }

// ============================ grid barrier ==================================
__device__ __forceinline__ void gsync(unsigned target){
  __syncthreads();
  if(threadIdx.x==0){
    unsigned* bp=&g_barrier;
    asm volatile("red.release.gpu.global.add.u32 [%0], 1;" :: "l"(bp) : "memory");
    unsigned v, ns=32;
    for(;;){
      asm volatile("ld.acquire.gpu.global.u32 %0, [%1];" : "=r"(v) : "l"(bp) : "memory");
      if(v>=target) break;
      __nanosleep(ns);
      if(ns<128) ns<<=1;
    }
  }
  __syncthreads();
}

// ==== pipelined small GEMM: 4 rows x 32 batch, K split across halves =======
template<int CK,int NCH>
__device__ __forceinline__ float pgemm(const float* __restrict__ W,
    const float* __restrict__ X, float* __restrict__ xs,
    int t, int half, int b){
  const int TOT=2*CK*32, PER=TOT/256;
  int cur=0; float acc=0.f;
#pragma unroll
  for(int j=0;j<PER;j++){
    int i=t+j*256, hf=i/(CK*32), i2=i-hf*CK*32, kk=i2>>5, bb=i2&31;
    xs[hf*CK*32+kk*32+bb]=X[(hf*(CK*NCH)+kk)*32+bb];
  }
  __syncthreads();
  for(int c=0;c<NCH;c++){
    float pf[PER];
    if(c+1<NCH){
#pragma unroll
      for(int j=0;j<PER;j++){
        int i=t+j*256, hf=i/(CK*32), i2=i-hf*CK*32, kk=i2>>5, bb=i2&31;
        pf[j]=X[(hf*(CK*NCH)+(c+1)*CK+kk)*32+bb];
      }
    }
    const float* w=W+c*CK;
    const float* xb=xs+cur*TOT+half*CK*32+b;
#pragma unroll
    for(int k=0;k<CK;k+=4){
      float4 w4=*(const float4*)&w[k];
      acc=fmaf(w4.x,xb[(k+0)*32],acc);
      acc=fmaf(w4.y,xb[(k+1)*32],acc);
      acc=fmaf(w4.z,xb[(k+2)*32],acc);
      acc=fmaf(w4.w,xb[(k+3)*32],acc);
    }
    if(c+1<NCH){
#pragma unroll
      for(int j=0;j<PER;j++){
        int i=t+j*256, hf=i/(CK*32), i2=i-hf*CK*32, kk=i2>>5, bb=i2&31;
        xs[(cur^1)*TOT+hf*CK*32+kk*32+bb]=pf[j];
      }
    }
    __syncthreads(); cur^=1;
  }
  return acc;
}

// ===================== persistent decoder: 128 blocks =======================
__global__ void __launch_bounds__(256,1) dec_k(const float* __restrict__ bl,
    const float* __restrict__ beta, const float* __restrict__ WO,
    const float* __restrict__ Wout, float* __restrict__ out){
  __shared__ __align__(16) union ShU{
    struct{ float x[2][2][64][32]; float red[128][4]; float gbuf[16][32]; } a;
    struct{ float xs[2][4096]; float red[128]; } p;
    struct{ float hp[512]; float bs[512]; } c;
    struct{ float e[512]; float rs[256]; float red[128]; } d;
  } sh;
  const int blk=blockIdx.x, t=threadIdx.x;
  const int half=t>>7, tl=t&127;
  unsigned bar=0;

  for(int ts=0;ts<=150;ts++){
    // ---- F: Q(ts-1) -> out ----
    if(ts>0 && blk<125){
      int row=blk*4+(tl>>5), b=tl&31;
      float acc=pgemm<64,4>(Wout+(size_t)row*512+half*256, g_xfull+80*32,
                            sh.p.xs[0], t, half, b);
      if(half==1) sh.p.red[tl]=acc;
      __syncthreads();
      if(half==0) out[(size_t)b*75000+(size_t)(ts-1)*500+row]=acc+sh.p.red[tl];
    }
    if(ts==150){ gsync(bar+=128); break; }
    __syncthreads();
    // ---- A: gates (unit-major) + fused LSTM ----
    {
      int rl=tl&15, cc=(tl>>4)*4;
      int rowp=blk*16+rl;
      const float* W=g_Wbig+(size_t)rowp*1152+half*576;
      float a0=0,a1=0,a2=0,a3=0; int cur=0;
#pragma unroll
      for(int j=0;j<16;j++){
        int i=t+j*256, hf=(i>=2048), i2=i-hf*2048, kk=i2>>5, bb=i2&31;
        sh.a.x[0][hf][kk][bb]=g_xfull[(hf*576+kk)*32+bb];
      }
      __syncthreads();
      for(int c=0;c<9;c++){
        float pf[16];
        if(c<8){
#pragma unroll
          for(int j=0;j<16;j++){
            int i=t+j*256, hf=(i>=2048), i2=i-hf*2048, kk=i2>>5, bb=i2&31;
            pf[j]=g_xfull[(hf*576+(c+1)*64+kk)*32+bb];
          }
        }
        const float* w=W+c*64;
#pragma unroll
        for(int k4=0;k4<64;k4+=4){
          float4 w4=*(const float4*)&w[k4];
          {const float* xv=&sh.a.x[cur][half][k4+0][cc];
           a0=fmaf(w4.x,xv[0],a0);a1=fmaf(w4.x,xv[1],a1);a2=fmaf(w4.x,xv[2],a2);a3=fmaf(w4.x,xv[3],a3);}
          {const float* xv=&sh.a.x[cur][half][k4+1][cc];
           a0=fmaf(w4.y,xv[0],a0);a1=fmaf(w4.y,xv[1],a1);a2=fmaf(w4.y,xv[2],a2);a3=fmaf(w4.y,xv[3],a3);}
          {const float* xv=&sh.a.x[cur][half][k4+2][cc];
           a0=fmaf(w4.z,xv[0],a0);a1=fmaf(w4.z,xv[1],a1);a2=fmaf(w4.z,xv[2],a2);a3=fmaf(w4.z,xv[3],a3);}
          {const float* xv=&sh.a.x[cur][half][k4+3][cc];
           a0=fmaf(w4.w,xv[0],a0);a1=fmaf(w4.w,xv[1],a1);a2=fmaf(w4.w,xv[2],a2);a3=fmaf(w4.w,xv[3],a3);}
        }
        if(c<8){
#pragma unroll
          for(int j=0;j<16;j++){
            int i=t+j*256, hf=(i>=2048), i2=i-hf*2048, kk=i2>>5, bb=i2&31;
            sh.a.x[cur^1][hf][kk][bb]=pf[j];
          }
        }
        __syncthreads(); cur^=1;
      }
      if(half==1){sh.a.red[tl][0]=a0;sh.a.red[tl][1]=a1;sh.a.red[tl][2]=a2;sh.a.red[tl][3]=a3;}
      __syncthreads();
      if(half==0){
        int unit=rowp>>2, gate=rowp&3;
        float bz=bl[gate*512+unit];
        sh.a.gbuf[rl][cc+0]=a0+sh.a.red[tl][0]+bz;
        sh.a.gbuf[rl][cc+1]=a1+sh.a.red[tl][1]+bz;
        sh.a.gbuf[rl][cc+2]=a2+sh.a.red[tl][2]+bz;
        sh.a.gbuf[rl][cc+3]=a3+sh.a.red[tl][3]+bz;
      }
      __syncthreads();
      if(t<128){
        int ul=t>>5, b=t&31, ug=blk*4+ul, p=ts&1;
        float iv=sh.a.gbuf[ul*4+0][b], fv=sh.a.gbuf[ul*4+1][b];
        float gv=sh.a.gbuf[ul*4+2][b], ov=sh.a.gbuf[ul*4+3][b];
        float cn=sigf(fv)*g_cT[p][ug*32+b]+sigf(iv)*tanhf(gv);
        float h=sigf(ov)*tanhf(cn);
        g_cT[p^1][ug*32+b]=cn;
        g_hc[ug*32+b]=h;
      }
    }
    gsync(bar+=128);

    // ---- hp = WhaT @ h ; republish h -> xfull ; stage next emb ----
    {
      int row=blk*4+(tl>>5), b=tl&31;
      float acc=pgemm<64,4>(g_WhaT+(size_t)row*512+half*256, g_hc,
                            sh.p.xs[0], t, half, b);
      if(half==1) sh.p.red[tl]=acc;
      __syncthreads();
      if(half==0) g_hp[row*32+b]=acc+sh.p.red[tl];
      int idx=blk*256+t;
      if(idx<16384) g_xfull[592*32+idx]=g_hc[idx];
      if(ts+1<150 && blk>=100 && blk<110){
        int base=(blk-100)*256;
        g_xfull[base+t]=g_embT[(size_t)(ts+1)*2560+base+t];
      }
    }
    gsync(bar+=128);

    // ---- scores -> es: hp/beta in regs, 4 l's in flight ----
    {
      int b=blk>>2, q=blk&3;
      for(int i=t;i<512;i+=256){ sh.c.hp[i]=g_hp[i*32+b]; sh.c.bs[i]=beta[i]; }
      __syncthreads();
      int w=t>>5, lane=t&31;
      float hpr[16], bsr[16];
#pragma unroll
      for(int i=0;i<16;i++){ hpr[i]=sh.c.hp[lane+(i<<5)]; bsr[i]=sh.c.bs[lane+(i<<5)]; }
#pragma unroll 1
      for(int lg=0;lg<4;lg++){
        int l=q*128+w*16+lg*4;
        const float* v0=g_VP+((size_t)(b*512+l)<<9);
        float s0=0,s1=0,s2=0,s3=0;
#pragma unroll
        for(int i=0;i<16;i++){
          int be=lane+(i<<5);
          float hb=hpr[i], bv=bsr[i];
          s0=fmaf(ftanh(v0[be     ]+hb),bv,s0);
          s1=fmaf(ftanh(v0[be+ 512]+hb),bv,s1);
          s2=fmaf(ftanh(v0[be+1024]+hb),bv,s2);
          s3=fmaf(ftanh(v0[be+1536]+hb),bv,s3);
        }
#pragma unroll
        for(int o=16;o;o>>=1){
          s0+=__shfl_xor_sync(0xffffffffu,s0,o);
          s1+=__shfl_xor_sync(0xffffffffu,s1,o);
          s2+=__shfl_xor_sync(0xffffffffu,s2,o);
          s3+=__shfl_xor_sync(0xffffffffu,s3,o);
        }
        if(lane==0)
          *(float4*)&g_es[b*512+l]=make_float4(__expf(s0),__expf(s1),__expf(s2),__expf(s3));
      }
    }
    gsync(bar+=128);

    // ---- ctx (2 independent FMA chains) ----
    {
      int b=blk>>2, cg2=blk&3;
      float s0=0.f;
      for(int i=t;i<512;i+=256){ float v=g_es[b*512+i]; sh.d.e[i]=v; s0+=v; }
      sh.d.rs[t]=s0; __syncthreads();
      for(int st=128;st;st>>=1){ if(t<st) sh.d.rs[t]+=sh.d.rs[t+st]; __syncthreads(); }
      float rs=sh.d.rs[0];
      int tc=t&127, th=t>>7, c=cg2*128+tc;
      const float* vb=g_V+((size_t)b<<18)+c;
      float acc0=0.f, acc1=0.f;
      for(int l0=th*256;l0<th*256+256;l0+=4){
        acc0=fmaf(sh.d.e[l0+0],vb[(size_t)(l0+0)<<9],acc0);
        acc1=fmaf(sh.d.e[l0+1],vb[(size_t)(l0+1)<<9],acc1);
        acc0=fmaf(sh.d.e[l0+2],vb[(size_t)(l0+2)<<9],acc0);
        acc1=fmaf(sh.d.e[l0+3],vb[(size_t)(l0+3)<<9],acc1);
      }
      float acc=acc0+acc1;
      if(th==1) sh.d.red[tc]=acc;
      __syncthreads();
      if(th==0) g_hc[(512+c)*32+b]=(acc+sh.d.red[tc])/rs;
    }
    gsync(bar+=128);

    // ---- O = tanh(WO @ hc) -> xfull O-section ----
    {
      int row=blk*4+(tl>>5), b=tl&31;
      float acc=pgemm<64,8>(WO+(size_t)row*1024+half*512, g_hc,
                            sh.p.xs[0], t, half, b);
      if(half==1) sh.p.red[tl]=acc;
      __syncthreads();
      if(half==0) g_xfull[(80+row)*32+b]=tanhf(acc+sh.p.red[tl]);
    }
    gsync(bar+=128);
  }
}

// ================================ launch ====================================
extern "C" void kernel_launch(void* const* d_in, const int* in_sizes, int n_in,
                              void* d_out, int out_size){
  const float* X   =(const float*)d_in[0];
  const int*   lab =(const int*)  d_in[1];
  const float* w1  =(const float*)d_in[2];  const float* b1=(const float*)d_in[3];
  const float* w2  =(const float*)d_in[4];  const float* b2=(const float*)d_in[5];
  const float* w3  =(const float*)d_in[6];  const float* b3=(const float*)d_in[7];
  const float* w4  =(const float*)d_in[8];  const float* b4=(const float*)d_in[9];
  const float* E   =(const float*)d_in[10];
  const float* Wx  =(const float*)d_in[11]; const float* Wh=(const float*)d_in[12];
  const float* bl  =(const float*)d_in[13];
  const float* Wv  =(const float*)d_in[14]; const float* Wha=(const float*)d_in[15];
  const float* batt=(const float*)d_in[16]; const float* beta=(const float*)d_in[17];
  const float* WO  =(const float*)d_in[18]; const float* Wout=(const float*)d_in[19];
  float* out=(float*)d_out;

  conv1_k<<<dim3(8,32,32),256>>>(X,w1,b1);
  conv2_k<<<dim3(4,16,64),256>>>(w2,b2);
  conv3_k<<<dim3(2,8,128),256>>>(w3,b3);
  conv4_k<<<dim3(2,8,256),256>>>(w4,b4);
  vproj_k<<<dim3(256,8),256>>>(Wv,batt);
  embT_k<<<1500,256>>>(lab,E);
  whaT_k<<<1024,256>>>(Wha);
  wbig_k<<<9216,256>>>(Wx,Wh);
  init_k<<<208,256>>>();
  dec_k<<<128,256>>>(bl,beta,WO,Wout,out);
  reset_k<<<1,1>>>();
}

// round 15
// speedup vs baseline: 1.2440x; 1.2440x over previous
#include <cuda_runtime.h>
#include <cstdint>
#include <cstddef>

typedef unsigned long long u64t;

__device__ float g_P1[16777216];
__device__ float g_P2[8388608];
__device__ float g_A3[16777216];
__device__ float g_V [8388608];
__device__ float g_VP[8388608];
__device__ float g_Wbig[2359296];  // [2048][1152] unit-major rows, K-padded
__device__ float g_WhaT[262144];
__device__ float g_embT[384000];
__device__ float g_xfull[36864];   // [1152][32]: emb80|O512|h512|pad
__device__ float g_cT[2][16384];
__device__ float g_hc[32768];      // [1024][32]: h | ctx
__device__ float g_hp[16384];
__device__ float g_es[16384];
__device__ float g_w1T[576];
__device__ float g_w2T[73728];
__device__ float g_w3T[294912];
__device__ float g_w4T[1179648];
__device__ unsigned g_barrier;

__device__ __forceinline__ float ftanh(float x){float y;asm("tanh.approx.f32 %0,%1;":"=f"(y):"f"(x));return y;}
__device__ __forceinline__ float sigf(float x){return 1.0f/(1.0f+__expf(-x));}
__device__ __forceinline__ u64t dupf(float v){u64t r;asm("mov.b64 %0,{%1,%1};":"=l"(r):"f"(v));return r;}
__device__ __forceinline__ void ffma2(u64t&a,u64t x,u64t w){asm("fma.rn.f32x2 %0,%1,%2,%3;":"=l"(a):"l"(x),"l"(w),"l"(a));}
__device__ __forceinline__ float2 unpk(u64t a){float2 f;asm("mov.b64 {%0,%1},%2;":"=f"(f.x),"=f"(f.y):"l"(a));return f;}

// ==== weight transpose: dst[((oct*ICQ+icq)*ICS+ic)*9*64 + k*64 + oc] ========
__global__ void wT_k(const float* __restrict__ w, float* __restrict__ dst,
                     int IC, int ICS, int OC){
  int u=blockIdx.x*256+threadIdx.x;
  int N=OC*IC*9; if(u>=N) return;
  int oc=u&63; int r=u>>6;
  int k=r%9; r/=9;
  int ic=r%ICS; r/=ICS;
  int ICQ=IC/ICS;
  int icq=r%ICQ; int oct=r/ICQ;
  dst[u]=w[(size_t)(oct*64+oc)*IC*9+(size_t)(icq*ICS+ic)*9+k];
}

// ================= conv3x3+bias+relu(+pool)(+NHWC), R6 body =================
// weights come pre-transposed: flat coalesced chunk per (oct, icb)
template<int IC,int ICS,bool POOL,bool TRANS>
__device__ __forceinline__ void conv_body(const float* __restrict__ wT,
    const float* __restrict__ bias, const float* __restrict__ in,
    float* __restrict__ out, int H, int W, int OC){
  __shared__ __align__(16) float wS[ICS*9*64];
  __shared__ __align__(16) float inS[ICS][4][66];
  const int tid=threadIdx.x, OCt=OC>>6, oct=blockIdx.z%OCt, n=blockIdx.z/OCt;
  const int ocb=oct*64, y0=blockIdx.y*2, x0=blockIdx.x*64;
  const int ocg=tid>>5, lane=tid&31, lane2=lane*2;
  u64t acc2[4][2][2];
#pragma unroll
  for(int op=0;op<4;op++){acc2[op][0][0]=0ull;acc2[op][0][1]=0ull;acc2[op][1][0]=0ull;acc2[op][1][1]=0ull;}
  for(int icb=0;icb<IC;icb+=ICS){
    const float* wc=wT+((size_t)oct*(IC/ICS)+icb/ICS)*(ICS*9*64);
    for(int i=tid*4;i<ICS*9*64;i+=1024)
      *(float4*)&wS[i]=*(const float4*)&wc[i];
    for(int i=tid;i<ICS*4*66;i+=256){
      int ic=i/264, rem=i-ic*264, r=rem/66, x=rem-r*66;
      int gy=y0-1+r, gx=x0-1+x; float v=0.f;
      if(gy>=0&&gy<H&&gx>=0&&gx<W) v=in[((size_t)(n*IC+icb+ic)*H+gy)*W+gx];
      inS[ic][r][x]=v;
    }
    __syncthreads();
#pragma unroll
    for(int ic=0;ic<ICS;ic++){
#pragma unroll
      for(int ky=0;ky<3;ky++){
        float2 p0=*(const float2*)&inS[ic][ky][lane2];
        float2 p1=*(const float2*)&inS[ic][ky][lane2+2];
        float2 q0=*(const float2*)&inS[ic][ky+1][lane2];
        float2 q1=*(const float2*)&inS[ic][ky+1][lane2+2];
        u64t dv0=dupf(p0.x),dv1=dupf(p0.y),dv2=dupf(p1.x),dv3=dupf(p1.y);
        u64t du0=dupf(q0.x),du1=dupf(q0.y),du2=dupf(q1.x),du3=dupf(q1.y);
#pragma unroll
        for(int op=0;op<4;op++){
          u64t w0=*(const u64t*)&wS[(ic*9+ky*3+0)*64+ocg*8+op*2];
          u64t w1=*(const u64t*)&wS[(ic*9+ky*3+1)*64+ocg*8+op*2];
          u64t w2=*(const u64t*)&wS[(ic*9+ky*3+2)*64+ocg*8+op*2];
          ffma2(acc2[op][0][0],dv0,w0); ffma2(acc2[op][0][0],dv1,w1); ffma2(acc2[op][0][0],dv2,w2);
          ffma2(acc2[op][0][1],dv1,w0); ffma2(acc2[op][0][1],dv2,w1); ffma2(acc2[op][0][1],dv3,w2);
          ffma2(acc2[op][1][0],du0,w0); ffma2(acc2[op][1][0],du1,w1); ffma2(acc2[op][1][0],du2,w2);
          ffma2(acc2[op][1][1],du1,w0); ffma2(acc2[op][1][1],du2,w1); ffma2(acc2[op][1][1],du3,w2);
        }
      }
    }
    __syncthreads();
  }
  float acc[8][2][2];
#pragma unroll
  for(int op=0;op<4;op++)
#pragma unroll
    for(int r=0;r<2;r++)
#pragma unroll
      for(int c=0;c<2;c++){
        float2 f=unpk(acc2[op][r][c]);
        acc[op*2][r][c]=f.x; acc[op*2+1][r][c]=f.y;
      }
  const int oc0=ocb+ocg*8;
  if(POOL){
    int py=y0>>1, px=(x0>>1)+lane; float pv[8];
#pragma unroll
    for(int o=0;o<8;o++){
      float bz=bias[oc0+o];
      pv[o]=fmaxf(fmaxf(fmaxf(acc[o][0][0]+bz,0.f),fmaxf(acc[o][0][1]+bz,0.f)),
                  fmaxf(fmaxf(acc[o][1][0]+bz,0.f),fmaxf(acc[o][1][1]+bz,0.f)));
    }
    if(TRANS){
      int l=py*(W>>1)+px;
      float* dst=g_V+((size_t)(n*((H>>1)*(W>>1))+l))*OC+oc0;
      *(float4*)&dst[0]=make_float4(pv[0],pv[1],pv[2],pv[3]);
      *(float4*)&dst[4]=make_float4(pv[4],pv[5],pv[6],pv[7]);
    }else{
      int Hp=H>>1,Wp=W>>1;
#pragma unroll
      for(int o=0;o<8;o++) out[((size_t)(n*OC+oc0+o)*Hp+py)*Wp+px]=pv[o];
    }
  }else{
#pragma unroll
    for(int o=0;o<8;o++){
      float bz=bias[oc0+o];
#pragma unroll
      for(int r=0;r<2;r++)
        *(float2*)&out[((size_t)(n*OC+oc0+o)*H+y0+r)*W+x0+lane2]=
          make_float2(fmaxf(acc[o][r][0]+bz,0.f),fmaxf(acc[o][r][1]+bz,0.f));
    }
  }
}
__global__ void __launch_bounds__(256) conv1_k(const float* X,const float* b){conv_body<1,1,true,false>(g_w1T,b,X,g_P1,64,512,64);}
__global__ void __launch_bounds__(256) conv2_k(const float* b){conv_body<64,8,true,false>(g_w2T,b,g_P1,g_P2,32,256,128);}
__global__ void __launch_bounds__(256) conv3_k(const float* b){conv_body<128,8,false,false>(g_w3T,b,g_P2,g_A3,16,128,256);}
__global__ void __launch_bounds__(256) conv4_k(const float* b){conv_body<256,8,true,true>(g_w4T,b,g_A3,g_V,16,128,512);}

// ==================== Vproj = V @ Wv + b, 64x64x16 tile =====================
__global__ void __launch_bounds__(256) vproj_k(const float* __restrict__ Bm,const float* __restrict__ bias){
  __shared__ float As[16][68]; __shared__ float Bs[16][64];
  int tid=threadIdx.x, m0=blockIdx.x*64, n0=blockIdx.y*64;
  int mi=tid>>4, ni=tid&15;
  float acc[4][4];
#pragma unroll
  for(int i=0;i<4;i++){acc[i][0]=acc[i][1]=acc[i][2]=acc[i][3]=0.f;}
  int arow=tid>>2, akq=(tid&3)*4, bk=tid>>4, bn=(tid&15)*4;
  for(int kb=0;kb<512;kb+=16){
    float4 a4=*(const float4*)&g_V[(size_t)(m0+arow)*512+kb+akq];
    As[akq+0][arow]=a4.x; As[akq+1][arow]=a4.y; As[akq+2][arow]=a4.z; As[akq+3][arow]=a4.w;
    *(float4*)&Bs[bk][bn]=*(const float4*)&Bm[(size_t)(kb+bk)*512+n0+bn];
    __syncthreads();
#pragma unroll
    for(int k=0;k<16;k++){
      float4 av=*(const float4*)&As[k][mi*4];
      float4 bv=*(const float4*)&Bs[k][ni*4];
      float am[4]={av.x,av.y,av.z,av.w}, bm[4]={bv.x,bv.y,bv.z,bv.w};
#pragma unroll
      for(int i=0;i<4;i++)
#pragma unroll
        for(int j=0;j<4;j++) acc[i][j]=fmaf(am[i],bm[j],acc[i][j]);
    }
    __syncthreads();
  }
  float4 b4=*(const float4*)&bias[n0+ni*4]; float bb[4]={b4.x,b4.y,b4.z,b4.w};
#pragma unroll
  for(int i=0;i<4;i++)
    *(float4*)&g_VP[(size_t)(m0+mi*4+i)*512+n0+ni*4]=
      make_float4(acc[i][0]+bb[0],acc[i][1]+bb[1],acc[i][2]+bb[2],acc[i][3]+bb[3]);
}

// ============================ setup =========================================
__global__ void embT_k(const int* __restrict__ labels,const float* __restrict__ E){
  int u=blockIdx.x*256+threadIdx.x; if(u>=150*2560) return;
  int t=u/2560, rem=u%2560, j=rem>>5, b=rem&31;
  int id=(t==0)?497:labels[b*150+t-1];
  g_embT[u]=E[id*80+j];
}
__global__ void whaT_k(const float* __restrict__ Wha){
  int u=blockIdx.x*256+threadIdx.x; if(u>=262144) return;
  int h=u>>9, be=u&511; g_WhaT[be*512+h]=Wha[u];
}
__global__ void wbig_k(const float* __restrict__ Wx,const float* __restrict__ Wh){
  int u=blockIdx.x*256+threadIdx.x; if(u>=2048*1152) return;
  int rp=u/1152, k=u-rp*1152;
  int unit=rp>>2, g=rp&3, orig=g*512+unit;
  float v=0.f;
  if(k<592) v=Wx[(size_t)orig*592+k];
  else if(k<1104) v=Wh[(size_t)orig*512+(k-592)];
  g_Wbig[u]=v;
}
__global__ void init_k(){
  int u=blockIdx.x*256+threadIdx.x;
  if(u<36864) g_xfull[u]=(u<2560)?g_embT[u]:0.f;
  else if(u<36864+16384) g_cT[0][u-36864]=0.f;
}
__global__ void reset_k(){ g_barrier=0u; }

// ============================ grid barrier ==================================
__device__ __forceinline__ void gsync(unsigned target){
  __syncthreads();
  if(threadIdx.x==0){
    unsigned* bp=&g_barrier;
    asm volatile("red.release.gpu.global.add.u32 [%0], 1;" :: "l"(bp) : "memory");
    unsigned v, ns=32;
    for(;;){
      asm volatile("ld.acquire.gpu.global.u32 %0, [%1];" : "=r"(v) : "l"(bp) : "memory");
      if(v>=target) break;
      __nanosleep(ns);
      if(ns<128) ns<<=1;
    }
  }
  __syncthreads();
}

// ==== pipelined small GEMM: 4 rows x 32 batch, K split across halves =======
template<int CK,int NCH>
__device__ __forceinline__ float pgemm(const float* __restrict__ W,
    const float* __restrict__ X, float* __restrict__ xs,
    int t, int half, int b){
  const int TOT=2*CK*32, PER=TOT/256;
  int cur=0; float acc=0.f;
#pragma unroll
  for(int j=0;j<PER;j++){
    int i=t+j*256, hf=i/(CK*32), i2=i-hf*CK*32, kk=i2>>5, bb=i2&31;
    xs[hf*CK*32+kk*32+bb]=X[(hf*(CK*NCH)+kk)*32+bb];
  }
  __syncthreads();
  for(int c=0;c<NCH;c++){
    float pf[PER];
    if(c+1<NCH){
#pragma unroll
      for(int j=0;j<PER;j++){
        int i=t+j*256, hf=i/(CK*32), i2=i-hf*CK*32, kk=i2>>5, bb=i2&31;
        pf[j]=X[(hf*(CK*NCH)+(c+1)*CK+kk)*32+bb];
      }
    }
    const float* w=W+c*CK;
    const float* xb=xs+cur*TOT+half*CK*32+b;
#pragma unroll
    for(int k=0;k<CK;k+=4){
      float4 w4=*(const float4*)&w[k];
      acc=fmaf(w4.x,xb[(k+0)*32],acc);
      acc=fmaf(w4.y,xb[(k+1)*32],acc);
      acc=fmaf(w4.z,xb[(k+2)*32],acc);
      acc=fmaf(w4.w,xb[(k+3)*32],acc);
    }
    if(c+1<NCH){
#pragma unroll
      for(int j=0;j<PER;j++){
        int i=t+j*256, hf=i/(CK*32), i2=i-hf*CK*32, kk=i2>>5, bb=i2&31;
        xs[(cur^1)*TOT+hf*CK*32+kk*32+bb]=pf[j];
      }
    }
    __syncthreads(); cur^=1;
  }
  return acc;
}

// ===================== persistent decoder: 128 blocks =======================
__global__ void __launch_bounds__(256,1) dec_k(const float* __restrict__ bl,
    const float* __restrict__ beta, const float* __restrict__ WO,
    const float* __restrict__ Wout, float* __restrict__ out){
  __shared__ __align__(16) union ShU{
    struct{ float x[2][2][64][32]; float red[128][4]; float gbuf[16][32]; } a;
    struct{ float xs[2][4096]; float red[128]; } p;
    struct{ float hp[512]; float bs[512]; } c;
    struct{ float e[512]; float rs[256]; float red[128]; } d;
  } sh;
  const int blk=blockIdx.x, t=threadIdx.x;
  const int half=t>>7, tl=t&127;
  unsigned bar=0;

  for(int ts=0;ts<=150;ts++){
    if(ts>0 && blk<125){
      int row=blk*4+(tl>>5), b=tl&31;
      float acc=pgemm<64,4>(Wout+(size_t)row*512+half*256, g_xfull+80*32,
                            sh.p.xs[0], t, half, b);
      if(half==1) sh.p.red[tl]=acc;
      __syncthreads();
      if(half==0) out[(size_t)b*75000+(size_t)(ts-1)*500+row]=acc+sh.p.red[tl];
    }
    if(ts==150){ gsync(bar+=128); break; }
    __syncthreads();
    // ---- gates (unit-major) + fused LSTM ----
    {
      int rl=tl&15, cc=(tl>>4)*4;
      int rowp=blk*16+rl;
      const float* W=g_Wbig+(size_t)rowp*1152+half*576;
      float a0=0,a1=0,a2=0,a3=0; int cur=0;
#pragma unroll
      for(int j=0;j<16;j++){
        int i=t+j*256, hf=(i>=2048), i2=i-hf*2048, kk=i2>>5, bb=i2&31;
        sh.a.x[0][hf][kk][bb]=g_xfull[(hf*576+kk)*32+bb];
      }
      __syncthreads();
      for(int c=0;c<9;c++){
        float pf[16];
        if(c<8){
#pragma unroll
          for(int j=0;j<16;j++){
            int i=t+j*256, hf=(i>=2048), i2=i-hf*2048, kk=i2>>5, bb=i2&31;
            pf[j]=g_xfull[(hf*576+(c+1)*64+kk)*32+bb];
          }
        }
        const float* w=W+c*64;
#pragma unroll
        for(int k4=0;k4<64;k4+=4){
          float4 w4=*(const float4*)&w[k4];
          {const float* xv=&sh.a.x[cur][half][k4+0][cc];
           a0=fmaf(w4.x,xv[0],a0);a1=fmaf(w4.x,xv[1],a1);a2=fmaf(w4.x,xv[2],a2);a3=fmaf(w4.x,xv[3],a3);}
          {const float* xv=&sh.a.x[cur][half][k4+1][cc];
           a0=fmaf(w4.y,xv[0],a0);a1=fmaf(w4.y,xv[1],a1);a2=fmaf(w4.y,xv[2],a2);a3=fmaf(w4.y,xv[3],a3);}
          {const float* xv=&sh.a.x[cur][half][k4+2][cc];
           a0=fmaf(w4.z,xv[0],a0);a1=fmaf(w4.z,xv[1],a1);a2=fmaf(w4.z,xv[2],a2);a3=fmaf(w4.z,xv[3],a3);}
          {const float* xv=&sh.a.x[cur][half][k4+3][cc];
           a0=fmaf(w4.w,xv[0],a0);a1=fmaf(w4.w,xv[1],a1);a2=fmaf(w4.w,xv[2],a2);a3=fmaf(w4.w,xv[3],a3);}
        }
        if(c<8){
#pragma unroll
          for(int j=0;j<16;j++){
            int i=t+j*256, hf=(i>=2048), i2=i-hf*2048, kk=i2>>5, bb=i2&31;
            sh.a.x[cur^1][hf][kk][bb]=pf[j];
          }
        }
        __syncthreads(); cur^=1;
      }
      if(half==1){sh.a.red[tl][0]=a0;sh.a.red[tl][1]=a1;sh.a.red[tl][2]=a2;sh.a.red[tl][3]=a3;}
      __syncthreads();
      if(half==0){
        int unit=rowp>>2, gate=rowp&3;
        float bz=bl[gate*512+unit];
        sh.a.gbuf[rl][cc+0]=a0+sh.a.red[tl][0]+bz;
        sh.a.gbuf[rl][cc+1]=a1+sh.a.red[tl][1]+bz;
        sh.a.gbuf[rl][cc+2]=a2+sh.a.red[tl][2]+bz;
        sh.a.gbuf[rl][cc+3]=a3+sh.a.red[tl][3]+bz;
      }
      __syncthreads();
      if(t<128){
        int ul=t>>5, b=t&31, ug=blk*4+ul, p=ts&1;
        float iv=sh.a.gbuf[ul*4+0][b], fv=sh.a.gbuf[ul*4+1][b];
        float gv=sh.a.gbuf[ul*4+2][b], ov=sh.a.gbuf[ul*4+3][b];
        float cn=sigf(fv)*g_cT[p][ug*32+b]+sigf(iv)*tanhf(gv);
        float h=sigf(ov)*tanhf(cn);
        g_cT[p^1][ug*32+b]=cn;
        g_hc[ug*32+b]=h;
      }
    }
    gsync(bar+=128);

    // ---- hp = WhaT @ h ; republish h -> xfull ; stage next emb ----
    {
      int row=blk*4+(tl>>5), b=tl&31;
      float acc=pgemm<64,4>(g_WhaT+(size_t)row*512+half*256, g_hc,
                            sh.p.xs[0], t, half, b);
      if(half==1) sh.p.red[tl]=acc;
      __syncthreads();
      if(half==0) g_hp[row*32+b]=acc+sh.p.red[tl];
      int idx=blk*256+t;
      if(idx<16384) g_xfull[592*32+idx]=g_hc[idx];
      if(ts+1<150 && blk>=100 && blk<110){
        int base=(blk-100)*256;
        g_xfull[base+t]=g_embT[(size_t)(ts+1)*2560+base+t];
      }
    }
    gsync(bar+=128);

    // ---- scores -> es ----
    {
      int b=blk>>2, q=blk&3;
      for(int i=t;i<512;i+=256){ sh.c.hp[i]=g_hp[i*32+b]; sh.c.bs[i]=beta[i]; }
      __syncthreads();
      int w=t>>5, lane=t&31;
#pragma unroll 1
      for(int li=0;li<16;li++){
        int l=q*128+w*16+li;
        const float* vp=g_VP+((size_t)(b*512+l)<<9);
        float s=0.f;
#pragma unroll
        for(int i=0;i<16;i++){int be=lane+(i<<5); s=fmaf(ftanh(vp[be]+sh.c.hp[be]),sh.c.bs[be],s);}
#pragma unroll
        for(int o=16;o;o>>=1) s+=__shfl_xor_sync(0xffffffffu,s,o);
        if(lane==0) g_es[b*512+l]=__expf(s);
      }
    }
    gsync(bar+=128);

    // ---- ctx ----
    {
      int b=blk>>2, cg2=blk&3;
      float s0=0.f;
      for(int i=t;i<512;i+=256){ float v=g_es[b*512+i]; sh.d.e[i]=v; s0+=v; }
      sh.d.rs[t]=s0; __syncthreads();
      for(int st=128;st;st>>=1){ if(t<st) sh.d.rs[t]+=sh.d.rs[t+st]; __syncthreads(); }
      float rs=sh.d.rs[0];
      int tc=t&127, th=t>>7, c=cg2*128+tc;
      const float* vb=g_V+((size_t)b<<18)+c;
      float acc=0.f;
      for(int l0=th*256;l0<th*256+256;l0+=4){
        acc=fmaf(sh.d.e[l0+0],vb[(size_t)(l0+0)<<9],acc);
        acc=fmaf(sh.d.e[l0+1],vb[(size_t)(l0+1)<<9],acc);
        acc=fmaf(sh.d.e[l0+2],vb[(size_t)(l0+2)<<9],acc);
        acc=fmaf(sh.d.e[l0+3],vb[(size_t)(l0+3)<<9],acc);
      }
      if(th==1) sh.d.red[tc]=acc;
      __syncthreads();
      if(th==0) g_hc[(512+c)*32+b]=(acc+sh.d.red[tc])/rs;
    }
    gsync(bar+=128);

    // ---- O = tanh(WO @ hc) -> xfull O-section ----
    {
      int row=blk*4+(tl>>5), b=tl&31;
      float acc=pgemm<64,8>(WO+(size_t)row*1024+half*512, g_hc,
                            sh.p.xs[0], t, half, b);
      if(half==1) sh.p.red[tl]=acc;
      __syncthreads();
      if(half==0) g_xfull[(80+row)*32+b]=tanhf(acc+sh.p.red[tl]);
    }
    gsync(bar+=128);
  }
}

// ================================ launch ====================================
extern "C" void kernel_launch(void* const* d_in, const int* in_sizes, int n_in,
                              void* d_out, int out_size){
  const float* X   =(const float*)d_in[0];
  const int*   lab =(const int*)  d_in[1];
  const float* w1  =(const float*)d_in[2];  const float* b1=(const float*)d_in[3];
  const float* w2  =(const float*)d_in[4];  const float* b2=(const float*)d_in[5];
  const float* w3  =(const float*)d_in[6];  const float* b3=(const float*)d_in[7];
  const float* w4  =(const float*)d_in[8];  const float* b4=(const float*)d_in[9];
  const float* E   =(const float*)d_in[10];
  const float* Wx  =(const float*)d_in[11]; const float* Wh=(const float*)d_in[12];
  const float* bl  =(const float*)d_in[13];
  const float* Wv  =(const float*)d_in[14]; const float* Wha=(const float*)d_in[15];
  const float* batt=(const float*)d_in[16]; const float* beta=(const float*)d_in[17];
  const float* WO  =(const float*)d_in[18]; const float* Wout=(const float*)d_in[19];
  float* out=(float*)d_out;

  float *w1T, *w2T, *w3T, *w4T;
  cudaGetSymbolAddress((void**)&w1T, g_w1T);
  cudaGetSymbolAddress((void**)&w2T, g_w2T);
  cudaGetSymbolAddress((void**)&w3T, g_w3T);
  cudaGetSymbolAddress((void**)&w4T, g_w4T);

  wT_k<<<3,256>>>(w1,w1T,1,1,64);
  wT_k<<<288,256>>>(w2,w2T,64,8,128);
  wT_k<<<1152,256>>>(w3,w3T,128,8,256);
  wT_k<<<4608,256>>>(w4,w4T,256,8,512);

  conv1_k<<<dim3(8,32,32),256>>>(X,b1);
  conv2_k<<<dim3(4,16,64),256>>>(b2);
  conv3_k<<<dim3(2,8,128),256>>>(b3);
  conv4_k<<<dim3(2,8,256),256>>>(b4);
  vproj_k<<<dim3(256,8),256>>>(Wv,batt);
  embT_k<<<1500,256>>>(lab,E);
  whaT_k<<<1024,256>>>(Wha);
  wbig_k<<<9216,256>>>(Wx,Wh);
  init_k<<<208,256>>>();
  dec_k<<<128,256>>>(bl,beta,WO,Wout,out);
  reset_k<<<1,1>>>();
}